// round 4
// baseline (speedup 1.0000x reference)
#include <cuda_runtime.h>
#include <cstdint>

// 3x3 erosion + dilation, fp32, NCHW (8,32,512,512), replicate border.
// Separable: horizontal 3-min/max via warp shuffles, vertical 3-reduce in
// registers. Software-pipelined: each iteration prefetches the NEXT two rows
// before computing the current two, so DRAM latency overlaps compute/stores.

#define NC      256      // N*C
#define H       512
#define W       512
#define ROWS    32       // rows per block strip
#define THREADS 128      // 128 * 4 floats = 512 = W

#define POS_INF __int_as_float(0x7f800000)
#define NEG_INF __int_as_float(0xff800000)

struct RowRaw {          // raw loaded row data for this thread
    float4 v;
    float  l, r;         // seam scalars (lanes 0 / 31 only)
};

struct RowMM {
    float4 mn;
    float4 mx;
};

__device__ __forceinline__ RowRaw load_row(const float* __restrict__ row,
                                           int xbase, int lane) {
    RowRaw rr;
    rr.v = *reinterpret_cast<const float4*>(row + xbase);
    rr.l = 0.0f;
    rr.r = 0.0f;
    if (lane == 0 && xbase > 0)       rr.l = row[xbase - 1];
    if (lane == 31 && xbase + 4 < W)  rr.r = row[xbase + 4];
    return rr;
}

// Horizontal 3-window min/max. Neighbors from warp shuffles; seam lanes use
// the prefetched scalars. Row-edge lanes use the identity (±inf).
__device__ __forceinline__ RowMM hmm(const RowRaw& rr, int xbase, int lane) {
    const float4 v = rr.v;
    float l = __shfl_up_sync(0xffffffffu, v.w, 1);
    float r = __shfl_down_sync(0xffffffffu, v.x, 1);
    if (lane == 0)  l = rr.l;
    if (lane == 31) r = rr.r;

    const bool lv = (xbase > 0);
    const bool rv = (xbase + 4 < W);
    const float lmn = lv ? l : POS_INF;
    const float lmx = lv ? l : NEG_INF;
    const float rmn = rv ? r : POS_INF;
    const float rmx = rv ? r : NEG_INF;

    RowMM o;
    o.mn.x = fminf(lmn, fminf(v.x, v.y));
    o.mn.y = fminf(v.x, fminf(v.y, v.z));
    o.mn.z = fminf(v.y, fminf(v.z, v.w));
    o.mn.w = fminf(v.z, fminf(v.w, rmn));

    o.mx.x = fmaxf(lmx, fmaxf(v.x, v.y));
    o.mx.y = fmaxf(v.x, fmaxf(v.y, v.z));
    o.mx.z = fmaxf(v.y, fmaxf(v.z, v.w));
    o.mx.w = fmaxf(v.z, fmaxf(v.w, rmx));
    return o;
}

__device__ __forceinline__ RowMM identity_row() {
    RowMM r;
    r.mn.x = r.mn.y = r.mn.z = r.mn.w = POS_INF;
    r.mx.x = r.mx.y = r.mx.z = r.mx.w = NEG_INF;
    return r;
}

__device__ __forceinline__ void vmerge_store(const RowMM& a, const RowMM& b,
                                             const RowMM& c,
                                             float* __restrict__ pd,
                                             float* __restrict__ pe,
                                             size_t off) {
    float4 omn, omx;
    omn.x = fminf(a.mn.x, fminf(b.mn.x, c.mn.x));
    omn.y = fminf(a.mn.y, fminf(b.mn.y, c.mn.y));
    omn.z = fminf(a.mn.z, fminf(b.mn.z, c.mn.z));
    omn.w = fminf(a.mn.w, fminf(b.mn.w, c.mn.w));

    omx.x = fmaxf(a.mx.x, fmaxf(b.mx.x, c.mx.x));
    omx.y = fmaxf(a.mx.y, fmaxf(b.mx.y, c.mx.y));
    omx.z = fmaxf(a.mx.z, fmaxf(b.mx.z, c.mx.z));
    omx.w = fmaxf(a.mx.w, fmaxf(b.mx.w, c.mx.w));

    __stcs(reinterpret_cast<float4*>(pd + off), omx);  // dilated = max
    __stcs(reinterpret_cast<float4*>(pe + off), omn);  // eroded  = min
}

__global__ void __launch_bounds__(THREADS, 8)
morph3x3_kernel(const float* __restrict__ x,
                float* __restrict__ dil,
                float* __restrict__ ero) {
    const int plane = blockIdx.y;
    const int strip = blockIdx.x;
    const int y0    = strip * ROWS;
    const int xbase = threadIdx.x * 4;
    const int lane  = threadIdx.x & 31;

    const float* p  = x   + (size_t)plane * H * W;
    float*       pd = dil + (size_t)plane * H * W;
    float*       pe = ero + (size_t)plane * H * W;

    // Prologue: prev = hmm(row y0-1) (identity at top edge), cur = hmm(row y0),
    // c1/c2 = raw rows y0+1, y0+2 (always in range: y0 <= H-ROWS).
    RowMM prev, cur;
    RowRaw c1, c2;
    {
        const int ym = (y0 == 0) ? 0 : (y0 - 1);
        RowRaw rm = load_row(p + (size_t)ym * W, xbase, lane);
        RowRaw rc = load_row(p + (size_t)y0 * W, xbase, lane);
        c1 = load_row(p + (size_t)(y0 + 1) * W, xbase, lane);
        c2 = load_row(p + (size_t)(y0 + 2) * W, xbase, lane);
        prev = hmm(rm, xbase, lane);
        cur  = hmm(rc, xbase, lane);
        if (y0 == 0) prev = identity_row();
    }

    // Main loop: iterations iy = 0..ROWS-4 step 2. Outputs rows y, y+1 using
    // rows y-1..y+2 (all register-resident). Prefetch rows y+3, y+4 FIRST so
    // their latency overlaps this iteration's compute + stores.
    #pragma unroll 2
    for (int iy = 0; iy <= ROWS - 4; iy += 2) {
        const int y  = y0 + iy;
        const int y3 = (y + 3 < H) ? (y + 3) : (H - 1);
        const int y4 = (y + 4 < H) ? (y + 4) : (H - 1);
        RowRaw w1 = load_row(p + (size_t)y3 * W, xbase, lane);
        RowRaw w2 = load_row(p + (size_t)y4 * W, xbase, lane);

        RowMM n1 = hmm(c1, xbase, lane);   // row y+1
        RowMM n2 = hmm(c2, xbase, lane);   // row y+2 (always < H here)

        const size_t o0 = (size_t)y * W + xbase;
        vmerge_store(prev, cur, n1, pd, pe, o0);
        vmerge_store(cur, n1, n2, pd, pe, o0 + W);

        prev = n1;
        cur  = n2;
        c1 = w1;
        c2 = w2;
    }

    // Peeled final iteration (iy = ROWS-2): no prefetch; bottom-edge fixup.
    {
        const int y = y0 + ROWS - 2;
        RowMM n1 = hmm(c1, xbase, lane);              // row y+1 (= y0+ROWS-1 < H)
        RowMM n2 = hmm(c2, xbase, lane);              // row y+2 (may be H)
        if (y + 2 >= H) n2 = identity_row();

        const size_t o0 = (size_t)y * W + xbase;
        vmerge_store(prev, cur, n1, pd, pe, o0);
        vmerge_store(cur, n1, n2, pd, pe, o0 + W);
    }
}

extern "C" void kernel_launch(void* const* d_in, const int* in_sizes, int n_in,
                              void* d_out, int out_size) {
    const float* x = (const float*)d_in[0];
    float* out = (float*)d_out;

    const size_t plane_elems = (size_t)NC * H * W;
    float* dil = out;                 // tuple order: (dilated, eroded)
    float* ero = out + plane_elems;

    dim3 grid(H / ROWS, NC);   // (16, 256)
    dim3 block(THREADS);
    morph3x3_kernel<<<grid, block>>>(x, dil, ero);
}